// round 3
// baseline (speedup 1.0000x reference)
#include <cuda_runtime.h>

// MemoryNet attention: q,k,v (4, 1024, 2048) fp32 channels-first, 8 heads, d_head=128.
// out (4, 1024, 2048) fp32, gamma scalar.
#define LL   2048
#define DH   128
#define BQ   128
#define BK   64
#define NKT  32
#define NT   256           // 8 warps

// smem layout (floats)
#define KS_STRIDE 72       // Ks[d][k]  (128 x 64, pad->72) : scalar b-loads conflict-free
#define VS_STRIDE 68       // Vs[d][ki] (128 x 64, pad->68)
#define PS_STRIDE 68       // Ps[q][ki]
#define KS_OFF  0
#define KS_SZ   (DH * KS_STRIDE)          // 9216  (x2 buffers)
#define VS_OFF  (KS_OFF + 2 * KS_SZ)      // 18432
#define VS_SZ   (DH * VS_STRIDE)          // 8704  (x2 buffers)
#define PS_OFF  (VS_OFF + 2 * VS_SZ)      // 35840
#define PS_SZ   (BQ * PS_STRIDE)          // 8704
#define SMEM_FLOATS (PS_OFF + PS_SZ)      // 44544
#define SMEM_BYTES  (SMEM_FLOATS * 4)     // 178176 B -> 1 CTA/SM
#define OUT_STRIDE 132                    // epilogue transpose buffer (reuses smem base)

__device__ __forceinline__ unsigned f2tf(float f) {
    unsigned r;
    asm("cvt.rna.tf32.f32 %0, %1;" : "=r"(r) : "f"(f));
    return r;
}

__device__ __forceinline__ void mma_tf32(float c[4], unsigned a0, unsigned a1,
                                         unsigned a2, unsigned a3,
                                         unsigned b0, unsigned b1) {
    asm volatile(
        "mma.sync.aligned.m16n8k8.row.col.f32.tf32.tf32.f32 "
        "{%0,%1,%2,%3}, {%4,%5,%6,%7}, {%8,%9}, {%0,%1,%2,%3};"
        : "+f"(c[0]), "+f"(c[1]), "+f"(c[2]), "+f"(c[3])
        : "r"(a0), "r"(a1), "r"(a2), "r"(a3), "r"(b0), "r"(b1));
}

__device__ __forceinline__ void cp16(unsigned dst_smem, const void* src) {
    asm volatile("cp.async.cg.shared.global [%0], [%1], 16;" :: "r"(dst_smem), "l"(src));
}
__device__ __forceinline__ void cp_commit() {
    asm volatile("cp.async.commit_group;");
}
template <int N>
__device__ __forceinline__ void cp_wait() {
    asm volatile("cp.async.wait_group %0;" :: "n"(N));
}

__global__ __launch_bounds__(NT, 1)
void attn_kernel(const float* __restrict__ qg, const float* __restrict__ kg,
                 const float* __restrict__ vg, const float* __restrict__ gamma,
                 float* __restrict__ out)
{
    extern __shared__ float smem[];
    float* Ps = smem + PS_OFF;
    const unsigned smem_u32 = (unsigned)__cvta_generic_to_shared(smem);

    const int tid  = threadIdx.x;
    const int w    = tid >> 5;
    const int lane = tid & 31;
    const int g    = lane >> 2;   // groupID (row within m16)
    const int tg   = lane & 3;    // thread-in-group (col within k8)
    const int qb   = w << 4;      // warp's q row base

    const int qt = blockIdx.x;              // 0..15
    const int bh = blockIdx.y;              // 0..31
    const size_t base = (size_t)bh * (DH * LL);
    const float* qp = qg + base;
    const float* kp = kg + base;
    const float* vp = vg + base;
    const int q0 = qt * BQ;

    const float scale = 0.08838834764831845f;   // 1/sqrt(128)

    // ---- preload Q fragments into registers (tf32-RNA, pre-scaled) ----
    unsigned qf[16][4];
    #pragma unroll
    for (int kk = 0; kk < 16; kk++) {
        const int d0 = 8 * kk;
        const float* c0 = qp + (size_t)(d0 + tg) * LL + q0 + qb + g;
        const float* c1 = qp + (size_t)(d0 + tg + 4) * LL + q0 + qb + g;
        qf[kk][0] = f2tf(c0[0] * scale);   // A[g   ][tg  ]
        qf[kk][1] = f2tf(c0[8] * scale);   // A[g+8 ][tg  ]
        qf[kk][2] = f2tf(c1[0] * scale);   // A[g   ][tg+4]
        qf[kk][3] = f2tf(c1[8] * scale);   // A[g+8 ][tg+4]
    }

    // cp.async mapping for K/V tiles: [128 d][64 k], 16B per thread per row-chunk
    const int kq = tid & 15;       // k = 4*kq
    const int dn = tid >> 4;       // d = dn + 16*m

    // ---- prologue: issue K_0 + V_0 as one group ----
    #pragma unroll
    for (int m = 0; m < 8; m++) {
        const int d = dn + 16 * m;
        cp16(smem_u32 + (KS_OFF + d * KS_STRIDE + 4 * kq) * 4,
             kp + (size_t)d * LL + 4 * kq);
        cp16(smem_u32 + (VS_OFF + d * VS_STRIDE + 4 * kq) * 4,
             vp + (size_t)d * LL + 4 * kq);
    }
    cp_commit();

    float o[16][4];
    #pragma unroll
    for (int nt = 0; nt < 16; nt++)
        #pragma unroll
        for (int i = 0; i < 4; i++) o[nt][i] = 0.0f;

    float m0 = -3.0e38f, m1 = -3.0e38f;
    float l0 = 0.0f, l1 = 0.0f;

    for (int t = 0; t < NKT; t++) {
        float* kb = smem + KS_OFF + (t & 1) * KS_SZ;
        float* vb = smem + VS_OFF + (t & 1) * VS_SZ;

        cp_wait<0>();      // tile t landed
        __syncthreads();   // visible CTA-wide; all warps done with tile t-1 buffers

        // ---- prefetch tile t+1 into the other buffers ----
        if (t + 1 < NKT) {
            const int kn0 = (t + 1) * BK;
            const unsigned kbo = (KS_OFF + ((t + 1) & 1) * KS_SZ) * 4;
            const unsigned vbo = (VS_OFF + ((t + 1) & 1) * VS_SZ) * 4;
            #pragma unroll
            for (int m = 0; m < 8; m++) {
                const int d = dn + 16 * m;
                cp16(smem_u32 + kbo + (d * KS_STRIDE + 4 * kq) * 4,
                     kp + (size_t)d * LL + kn0 + 4 * kq);
                cp16(smem_u32 + vbo + (d * VS_STRIDE + 4 * kq) * 4,
                     vp + (size_t)d * LL + kn0 + 4 * kq);
            }
            cp_commit();
        }

        // ---- in-place tf32-RNA conversion of K and V tiles (once per element) ----
        {
            float4* k4 = (float4*)kb;
            #pragma unroll
            for (int i = 0; i < 9; i++) {        // 9216/4 = 2304 = 9*256
                float4 x = k4[tid + 256 * i];
                x.x = __uint_as_float(f2tf(x.x));
                x.y = __uint_as_float(f2tf(x.y));
                x.z = __uint_as_float(f2tf(x.z));
                x.w = __uint_as_float(f2tf(x.w));
                k4[tid + 256 * i] = x;
            }
            float4* v4 = (float4*)vb;
            #pragma unroll
            for (int i = 0; i < 8; i++) {        // 8704/4 = 2176 = 8*256 + 128
                float4 x = v4[tid + 256 * i];
                x.x = __uint_as_float(f2tf(x.x));
                x.y = __uint_as_float(f2tf(x.y));
                x.z = __uint_as_float(f2tf(x.z));
                x.w = __uint_as_float(f2tf(x.w));
                v4[tid + 256 * i] = x;
            }
            if (tid < 128) {
                float4 x = v4[2048 + tid];
                x.x = __uint_as_float(f2tf(x.x));
                x.y = __uint_as_float(f2tf(x.y));
                x.z = __uint_as_float(f2tf(x.z));
                x.w = __uint_as_float(f2tf(x.w));
                v4[2048 + tid] = x;
            }
        }
        __syncthreads();   // converted tiles visible

        // ---- GEMM1: S[16q][64k] = Q·K^T (A from registers, B raw tf32 bits) ----
        float s[8][4];
        #pragma unroll
        for (int nt = 0; nt < 8; nt++)
            #pragma unroll
            for (int i = 0; i < 4; i++) s[nt][i] = 0.0f;

        #pragma unroll 4
        for (int kk = 0; kk < 16; kk++) {
            const float* kcol = kb + (8 * kk + tg) * KS_STRIDE + g;
            #pragma unroll
            for (int nt = 0; nt < 8; nt++) {
                const unsigned b0 = __float_as_uint(kcol[8 * nt]);
                const unsigned b1 = __float_as_uint(kcol[4 * KS_STRIDE + 8 * nt]);
                mma_tf32(s[nt], qf[kk][0], qf[kk][1], qf[kk][2], qf[kk][3], b0, b1);
            }
        }

        // ---- online softmax (rows qb+g, qb+g+8 owned by this warp's 4-lane group) ----
        {
            float tm0 = -3.0e38f, tm1 = -3.0e38f;
            #pragma unroll
            for (int nt = 0; nt < 8; nt++) {
                tm0 = fmaxf(tm0, fmaxf(s[nt][0], s[nt][1]));
                tm1 = fmaxf(tm1, fmaxf(s[nt][2], s[nt][3]));
            }
            tm0 = fmaxf(tm0, __shfl_xor_sync(0xffffffffu, tm0, 1));
            tm0 = fmaxf(tm0, __shfl_xor_sync(0xffffffffu, tm0, 2));
            tm1 = fmaxf(tm1, __shfl_xor_sync(0xffffffffu, tm1, 1));
            tm1 = fmaxf(tm1, __shfl_xor_sync(0xffffffffu, tm1, 2));
            const float mn0 = fmaxf(m0, tm0);
            const float mn1 = fmaxf(m1, tm1);
            const float al0 = __expf(m0 - mn0);
            const float al1 = __expf(m1 - mn1);
            float sum0 = 0.0f, sum1 = 0.0f;
            float* pr0 = Ps + (qb + g) * PS_STRIDE + 2 * tg;
            float* pr1 = pr0 + 8 * PS_STRIDE;
            #pragma unroll
            for (int nt = 0; nt < 8; nt++) {
                const float p00 = __expf(s[nt][0] - mn0);
                const float p01 = __expf(s[nt][1] - mn0);
                const float p10 = __expf(s[nt][2] - mn1);
                const float p11 = __expf(s[nt][3] - mn1);
                sum0 += p00 + p01;
                sum1 += p10 + p11;
                pr0[8 * nt]     = __uint_as_float(f2tf(p00));
                pr0[8 * nt + 1] = __uint_as_float(f2tf(p01));
                pr1[8 * nt]     = __uint_as_float(f2tf(p10));
                pr1[8 * nt + 1] = __uint_as_float(f2tf(p11));
            }
            sum0 += __shfl_xor_sync(0xffffffffu, sum0, 1);
            sum0 += __shfl_xor_sync(0xffffffffu, sum0, 2);
            sum1 += __shfl_xor_sync(0xffffffffu, sum1, 1);
            sum1 += __shfl_xor_sync(0xffffffffu, sum1, 2);
            l0 = l0 * al0 + sum0;
            l1 = l1 * al1 + sum1;
            m0 = mn0; m1 = mn1;
            #pragma unroll
            for (int nt = 0; nt < 16; nt++) {
                o[nt][0] *= al0; o[nt][1] *= al0;
                o[nt][2] *= al1; o[nt][3] *= al1;
            }
        }
        __syncwarp();   // P rows are warp-private: warp-level fence suffices

        // ---- GEMM2: O[16q][128d] += P·V ----
        #pragma unroll 2
        for (int kk = 0; kk < 8; kk++) {
            const int ki0 = kk * 8;
            const float* prow = Ps + (qb + g) * PS_STRIDE + ki0 + tg;
            const unsigned a0 = __float_as_uint(prow[0]);
            const unsigned a2 = __float_as_uint(prow[4]);
            const unsigned a1 = __float_as_uint(prow[8 * PS_STRIDE]);
            const unsigned a3 = __float_as_uint(prow[8 * PS_STRIDE + 4]);
            #pragma unroll
            for (int nt = 0; nt < 16; nt++) {
                const float* vcol = vb + (8 * nt + g) * VS_STRIDE + ki0 + tg;
                const unsigned b0 = __float_as_uint(vcol[0]);
                const unsigned b1 = __float_as_uint(vcol[4]);
                mma_tf32(o[nt], a0, a1, a2, a3, b0, b1);
            }
        }
    }

    // ---- epilogue: O/l * gamma, transpose through smem, coalesced store ----
    const float gm = *gamma;
    const float inv0 = gm / l0;
    const float inv1 = gm / l1;

    __syncthreads();                 // done with pipeline buffers
    float* sOut = smem;              // [d][q], stride OUT_STRIDE (16896 floats, fits)
    #pragma unroll
    for (int nt = 0; nt < 16; nt++) {
        const int d0 = 8 * nt + 2 * tg;
        sOut[(d0    ) * OUT_STRIDE + qb + g    ] = o[nt][0] * inv0;
        sOut[(d0 + 1) * OUT_STRIDE + qb + g    ] = o[nt][1] * inv0;
        sOut[(d0    ) * OUT_STRIDE + qb + g + 8] = o[nt][2] * inv1;
        sOut[(d0 + 1) * OUT_STRIDE + qb + g + 8] = o[nt][3] * inv1;
    }
    __syncthreads();

    #pragma unroll
    for (int it = 0; it < 16; it++) {
        const int idx = tid + NT * it;     // 4096 float4s = 128 d x 32 q-quads
        const int d  = idx >> 5;
        const int qv = idx & 31;
        float4 tt = *(const float4*)(sOut + d * OUT_STRIDE + 4 * qv);
        *(float4*)(out + base + (size_t)d * LL + q0 + 4 * qv) = tt;
    }
}

extern "C" void kernel_launch(void* const* d_in, const int* in_sizes, int n_in,
                              void* d_out, int out_size)
{
    const float* q     = (const float*)d_in[0];
    const float* k     = (const float*)d_in[1];
    const float* v     = (const float*)d_in[2];
    const float* gamma = (const float*)d_in[3];
    float* out = (float*)d_out;

    cudaFuncSetAttribute(attn_kernel, cudaFuncAttributeMaxDynamicSharedMemorySize, SMEM_BYTES);

    dim3 grid(LL / BQ, 32);    // 16 q-tiles x (4 batch * 8 heads) = 512 CTAs
    attn_kernel<<<grid, NT, SMEM_BYTES>>>(q, k, v, gamma, out);
}

// round 5
// speedup vs baseline: 1.4059x; 1.4059x over previous
#include <cuda_runtime.h>
#include <cuda_fp16.h>

// MemoryNet attention: q,k,v (4, 1024, 2048) fp32 channels-first, 8 heads, d_head=128.
// fp16 HMMA (m16n8k16) flash-attention. out fp32, gamma scalar.
#define LL   2048
#define DH   128
#define BQ   128
#define BK   64
#define NKT  32
#define NT   256           // 8 warps, each owns 16 q-rows

// smem layout in HALF units
#define QS_STR 136         // Q [128 q][128 d]  (stride 68 words ≡ 4 mod 32 -> conflict-free A loads)
#define KS_STR 130         // K [64 key][128 d] (stride 65 words; cols XOR-swizzled by key&7)
#define VS_STR 72          // V [128 dv][64 ki] (stride 36 words ≡ 4)
#define PS_STR 72          // P [128 q][64 ki]
#define QS_OFF 0
#define KS_OFF 17408                     // 128*136
#define KS_SZ  (64 * KS_STR)             // 8320 per buffer, x2
#define VS_OFF (KS_OFF + 2 * KS_SZ)      // 34048
#define VS_SZ  (128 * VS_STR)            // 9216 per buffer, x2
#define PS_OFF (VS_OFF + 2 * VS_SZ)      // 52480
#define SMEM_HALVES (PS_OFF + 128 * PS_STR)   // 61696
#define SMEM_BYTES  (SMEM_HALVES * 2)         // 123392
#define OUT_STRIDE 132                   // epilogue float buffer [d][q] (reuses smem)

static __device__ __forceinline__ void mma16(float c[4], unsigned a0, unsigned a1,
                                             unsigned a2, unsigned a3,
                                             unsigned b0, unsigned b1) {
    asm volatile(
        "mma.sync.aligned.m16n8k16.row.col.f32.f16.f16.f32 "
        "{%0,%1,%2,%3}, {%4,%5,%6,%7}, {%8,%9}, {%0,%1,%2,%3};"
        : "+f"(c[0]), "+f"(c[1]), "+f"(c[2]), "+f"(c[3])
        : "r"(a0), "r"(a1), "r"(a2), "r"(a3), "r"(b0), "r"(b1));
}
static __device__ __forceinline__ unsigned ldu(const __half* p) {
    return *(const unsigned*)p;
}

__global__ __launch_bounds__(NT, 1)
void attn_kernel(const float* __restrict__ qg, const float* __restrict__ kg,
                 const float* __restrict__ vg, const float* __restrict__ gamma,
                 float* __restrict__ out)
{
    extern __shared__ __half sm[];
    __half* Qs = sm + QS_OFF;
    __half* Ps = sm + PS_OFF;

    const int tid  = threadIdx.x;
    const int w    = tid >> 5;
    const int lane = tid & 31;
    const int g    = lane >> 2;   // groupID: m-row / n-col within fragment
    const int tg   = lane & 3;    // thread-in-group: k pairs
    const int qb   = w << 4;      // warp's q base

    const int qt = blockIdx.x;              // 0..15
    const int bh = blockIdx.y;              // 0..31
    const size_t base = (size_t)bh * ((size_t)DH * LL);
    const float* qp = qg + base;
    const float* kp = kg + base;
    const float* vp = vg + base;
    const int q0 = qt * BQ;
    const float scale = 0.08838834764831845f;   // 1/sqrt(128)

    // staging thread mapping (coalesced float4 LDG along L)
    const int kq  = tid & 15;      // key/ki = 4*kq
    const int dl  = tid >> 4;      // d base

    // ---- prologue: Q -> smem [q][d] half (transposed, scaled) ----
    {
        const int q4 = tid & 31, dq = tid >> 5;
        #pragma unroll
        for (int m = 0; m < 16; m++) {
            const int d = dq + 8 * m;
            float4 t = *(const float4*)(qp + (size_t)d * LL + q0 + 4 * q4);
            Qs[(4 * q4 + 0) * QS_STR + d] = __float2half_rn(t.x * scale);
            Qs[(4 * q4 + 1) * QS_STR + d] = __float2half_rn(t.y * scale);
            Qs[(4 * q4 + 2) * QS_STR + d] = __float2half_rn(t.z * scale);
            Qs[(4 * q4 + 3) * QS_STR + d] = __float2half_rn(t.w * scale);
        }
    }
    // ---- prologue: K_0 / V_0 ----
    {
        #pragma unroll
        for (int m = 0; m < 8; m++) {
            const int d = dl + 16 * m;
            float4 t = *(const float4*)(kp + (size_t)d * LL + 4 * kq);
            __half* kb = sm + KS_OFF;
            #pragma unroll
            for (int j = 0; j < 4; j++) {
                const int key = 4 * kq + j;
                const float v = (j == 0) ? t.x : (j == 1) ? t.y : (j == 2) ? t.z : t.w;
                kb[key * KS_STR + (d ^ ((key & 7) << 4))] = __float2half_rn(v);
            }
        }
        #pragma unroll
        for (int m = 0; m < 8; m++) {
            const int dv = dl + 16 * m;
            float4 t = *(const float4*)(vp + (size_t)dv * LL + 4 * kq);
            __half* vb = sm + VS_OFF;
            *(__half2*)(vb + dv * VS_STR + 4 * kq)     = __floats2half2_rn(t.x, t.y);
            *(__half2*)(vb + dv * VS_STR + 4 * kq + 2) = __floats2half2_rn(t.z, t.w);
        }
    }

    float o[16][4];
    #pragma unroll
    for (int nt = 0; nt < 16; nt++)
        #pragma unroll
        for (int i = 0; i < 4; i++) o[nt][i] = 0.0f;

    float m0 = -3.0e38f, m1 = -3.0e38f;
    float l0 = 0.0f, l1 = 0.0f;

    for (int t = 0; t < NKT; t++) {
        const __half* kb = sm + KS_OFF + (t & 1) * KS_SZ;
        const __half* vb = sm + VS_OFF + (t & 1) * VS_SZ;
        const bool pf = (t + 1 < NKT);
        const int kn = (t + 1) * BK;

        __syncthreads();   // tile t staged & visible; buffers (t+1)&1 free

        // ---- issue K_{t+1} loads (consumed after GEMM1) ----
        float4 kreg[8];
        if (pf) {
            #pragma unroll
            for (int m = 0; m < 8; m++)
                kreg[m] = *(const float4*)(kp + (size_t)(dl + 16 * m) * LL + kn + 4 * kq);
        }

        // ---- GEMM1: S[16q][64k] = Q·K^T ----
        float s[8][4];
        #pragma unroll
        for (int nt = 0; nt < 8; nt++)
            #pragma unroll
            for (int i = 0; i < 4; i++) s[nt][i] = 0.0f;

        const __half* qrow = Qs + (qb + g) * QS_STR + 2 * tg;
        #pragma unroll
        for (int kk = 0; kk < 8; kk++) {
            const unsigned a0 = ldu(qrow + 16 * kk);
            const unsigned a1 = ldu(qrow + 16 * kk + 8 * QS_STR);
            const unsigned a2 = ldu(qrow + 16 * kk + 8);
            const unsigned a3 = ldu(qrow + 16 * kk + 8 * QS_STR + 8);
            // key-XOR swizzle: phys col base = 16*(kk ^ (key&7)), key&7 == g
            const __half* kcol = kb + g * KS_STR + 16 * (kk ^ g) + 2 * tg;
            #pragma unroll
            for (int nt = 0; nt < 8; nt++) {
                const unsigned b0 = ldu(kcol + 8 * nt * KS_STR);
                const unsigned b1 = ldu(kcol + 8 * nt * KS_STR + 8);
                mma16(s[nt], a0, a1, a2, a3, b0, b1);
            }
        }

        // ---- commit K_{t+1} to smem (LDGs long since landed) ----
        if (pf) {
            __half* kd = sm + KS_OFF + ((t + 1) & 1) * KS_SZ;
            #pragma unroll
            for (int m = 0; m < 8; m++) {
                const int d = dl + 16 * m;
                const float4 x = kreg[m];
                #pragma unroll
                for (int j = 0; j < 4; j++) {
                    const int key = 4 * kq + j;
                    const float v = (j == 0) ? x.x : (j == 1) ? x.y : (j == 2) ? x.z : x.w;
                    kd[key * KS_STR + (d ^ ((key & 7) << 4))] = __float2half_rn(v);
                }
            }
        }

        // ---- online softmax; P (half) is warp-private ----
        {
            float tm0 = -3.0e38f, tm1 = -3.0e38f;
            #pragma unroll
            for (int nt = 0; nt < 8; nt++) {
                tm0 = fmaxf(tm0, fmaxf(s[nt][0], s[nt][1]));
                tm1 = fmaxf(tm1, fmaxf(s[nt][2], s[nt][3]));
            }
            tm0 = fmaxf(tm0, __shfl_xor_sync(0xffffffffu, tm0, 1));
            tm0 = fmaxf(tm0, __shfl_xor_sync(0xffffffffu, tm0, 2));
            tm1 = fmaxf(tm1, __shfl_xor_sync(0xffffffffu, tm1, 1));
            tm1 = fmaxf(tm1, __shfl_xor_sync(0xffffffffu, tm1, 2));
            const float mn0 = fmaxf(m0, tm0);
            const float mn1 = fmaxf(m1, tm1);
            const float al0 = __expf(m0 - mn0);
            const float al1 = __expf(m1 - mn1);
            float sum0 = 0.0f, sum1 = 0.0f;
            __half* pr0 = Ps + (qb + g) * PS_STR + 2 * tg;
            __half* pr1 = pr0 + 8 * PS_STR;
            #pragma unroll
            for (int nt = 0; nt < 8; nt++) {
                const float p00 = __expf(s[nt][0] - mn0);
                const float p01 = __expf(s[nt][1] - mn0);
                const float p10 = __expf(s[nt][2] - mn1);
                const float p11 = __expf(s[nt][3] - mn1);
                sum0 += p00 + p01;
                sum1 += p10 + p11;
                *(__half2*)(pr0 + 8 * nt) = __floats2half2_rn(p00, p01);
                *(__half2*)(pr1 + 8 * nt) = __floats2half2_rn(p10, p11);
            }
            sum0 += __shfl_xor_sync(0xffffffffu, sum0, 1);
            sum0 += __shfl_xor_sync(0xffffffffu, sum0, 2);
            sum1 += __shfl_xor_sync(0xffffffffu, sum1, 1);
            sum1 += __shfl_xor_sync(0xffffffffu, sum1, 2);
            l0 = l0 * al0 + sum0;
            l1 = l1 * al1 + sum1;
            m0 = mn0; m1 = mn1;
            #pragma unroll
            for (int nt = 0; nt < 16; nt++) {
                o[nt][0] *= al0; o[nt][1] *= al0;
                o[nt][2] *= al1; o[nt][3] *= al1;
            }
        }

        // ---- issue V_{t+1} loads (consumed after GEMM2) ----
        float4 vreg[8];
        if (pf) {
            #pragma unroll
            for (int m = 0; m < 8; m++)
                vreg[m] = *(const float4*)(vp + (size_t)(dl + 16 * m) * LL + kn + 4 * kq);
        }

        __syncwarp();   // P rows visible within the warp

        // ---- GEMM2: O[16q][128d] += P·V ----
        const __half* prow = Ps + (qb + g) * PS_STR + 2 * tg;
        #pragma unroll
        for (int kk = 0; kk < 4; kk++) {
            const unsigned a0 = ldu(prow + 16 * kk);
            const unsigned a1 = ldu(prow + 16 * kk + 8 * PS_STR);
            const unsigned a2 = ldu(prow + 16 * kk + 8);
            const unsigned a3 = ldu(prow + 16 * kk + 8 * PS_STR + 8);
            const __half* vcol = vb + g * VS_STR + 16 * kk + 2 * tg;
            #pragma unroll
            for (int nt = 0; nt < 16; nt++) {
                const unsigned b0 = ldu(vcol + 8 * nt * VS_STR);
                const unsigned b1 = ldu(vcol + 8 * nt * VS_STR + 8);
                mma16(o[nt], a0, a1, a2, a3, b0, b1);
            }
        }

        // ---- commit V_{t+1} ----
        if (pf) {
            __half* vd = sm + VS_OFF + ((t + 1) & 1) * VS_SZ;
            #pragma unroll
            for (int m = 0; m < 8; m++) {
                const int dv = dl + 16 * m;
                const float4 x = vreg[m];
                *(__half2*)(vd + dv * VS_STR + 4 * kq)     = __floats2half2_rn(x.x, x.y);
                *(__half2*)(vd + dv * VS_STR + 4 * kq + 2) = __floats2half2_rn(x.z, x.w);
            }
        }
    }

    // ---- epilogue: O/l * gamma, transpose through smem, coalesced float4 stores ----
    const float gm = *gamma;
    const float inv0 = gm / l0;
    const float inv1 = gm / l1;

    __syncthreads();
    float* sOut = (float*)sm;        // [d][q] floats, stride OUT_STRIDE (67584 B, fits)
    #pragma unroll
    for (int nt = 0; nt < 16; nt++) {
        const int d0 = 8 * nt + 2 * tg;
        sOut[(d0    ) * OUT_STRIDE + qb + g    ] = o[nt][0] * inv0;
        sOut[(d0 + 1) * OUT_STRIDE + qb + g    ] = o[nt][1] * inv0;
        sOut[(d0    ) * OUT_STRIDE + qb + g + 8] = o[nt][2] * inv1;
        sOut[(d0 + 1) * OUT_STRIDE + qb + g + 8] = o[nt][3] * inv1;
    }
    __syncthreads();

    #pragma unroll
    for (int it = 0; it < 16; it++) {
        const int idx = tid + NT * it;     // 4096 float4s = 128 d x 32 q-quads
        const int d  = idx >> 5;
        const int qv = idx & 31;
        float4 tt = *(const float4*)(sOut + d * OUT_STRIDE + 4 * qv);
        *(float4*)(out + base + (size_t)d * LL + q0 + 4 * qv) = tt;
    }
}

extern "C" void kernel_launch(void* const* d_in, const int* in_sizes, int n_in,
                              void* d_out, int out_size)
{
    const float* q     = (const float*)d_in[0];
    const float* k     = (const float*)d_in[1];
    const float* v     = (const float*)d_in[2];
    const float* gamma = (const float*)d_in[3];
    float* out = (float*)d_out;

    cudaFuncSetAttribute(attn_kernel, cudaFuncAttributeMaxDynamicSharedMemorySize, SMEM_BYTES);

    dim3 grid(LL / BQ, 32);    // 16 q-tiles x 32 (b,h) = 512 CTAs
    attn_kernel<<<grid, NT, SMEM_BYTES>>>(q, k, v, gamma, out);
}